// round 4
// baseline (speedup 1.0000x reference)
#include <cuda_runtime.h>
#include <cuda_bf16.h>
#include <cstdint>

// Problem: RNN_28621662060981
//   x[256,128] int32 -> emb[32000,2048] -> xproj GEMM -> 256-step tanh RNN -> MLP head
// Inputs (metadata order): x, emb, W_ih, W_hh, b_ih, b_hh, fc1_w, fc1_b, fc2_w, fc2_b
// Output: float32 [128,3]

#define T_STEPS 256
#define BATCH   128
#define EMBD    2048
#define HID     2048
#define ROWS    (T_STEPS * BATCH)   // 32768

// Scan decomposition: 16 N-slices (128 cols) x 8 K-splits (256 k) = 128 CTAs.
#define NSL   16
#define KSPL  8
#define WN    128                   // output cols per slice
#define KC    256                   // k-range per CTA
#define SCAN_CTAS (NSL * KSPL)      // 128

// Smem (dynamic; static __shared__ limit is 48KB)
#define WS_PITCH 260                // 260 mod 32 = 4 -> b-fragment banks 4g+8ks+c, conflict-free
#define SCAN_SMEM (128 * WS_PITCH * 4 + 2 * 128 * 36 * 4)    // 133120 + 36864 = 169984
#define EMB_SMEM  (2 * 128 * 36 * 4 + 2 * 64 * 36 * 4 + 512) // 36864 + 18432 + 512 = 55808

// ---------------- scratch (device globals: allocation-free rule) ----------------
__device__ float    g_xproj[ROWS * HID];                  // 256 MB
__device__ float    g_h[2][BATCH * HID];                  // double-buffered hidden state
__device__ float    g_part[NSL * KSPL * BATCH * WN];      // 8 MB partial exchange
__device__ unsigned g_ctr;                                // grid barrier counter

// ---------------- helpers ----------------
__device__ __forceinline__ uint32_t f2tf32(float f) {
    uint32_t u;
    asm("cvt.rna.tf32.f32 %0, %1;" : "=r"(u) : "f"(f));
    return u;
}

__device__ __forceinline__ void mma_tf32(float* c, const uint32_t* a, const uint32_t* b) {
    asm volatile(
        "mma.sync.aligned.m16n8k8.row.col.f32.tf32.tf32.f32 "
        "{%0,%1,%2,%3}, {%4,%5,%6,%7}, {%8,%9}, {%0,%1,%2,%3};\n"
        : "+f"(c[0]), "+f"(c[1]), "+f"(c[2]), "+f"(c[3])
        : "r"(a[0]), "r"(a[1]), "r"(a[2]), "r"(a[3]), "r"(b[0]), "r"(b[1]));
}

// Release-add + acquire-spin grid barrier step (tid==0 only), then bar.sync outside.
__device__ __forceinline__ void grid_bar(unsigned target) {
    unsigned old;
    asm volatile("atom.release.gpu.global.add.u32 %0, [%1], %2;"
                 : "=r"(old) : "l"(&g_ctr), "r"(1u));
    unsigned v;
    do {
        asm volatile("ld.acquire.gpu.global.u32 %0, [%1];" : "=r"(v) : "l"(&g_ctr));
    } while (v < target);
}

// ---------------- init: zero h0 + barrier counter (every launch, for graph replay) ----
__global__ void init_kernel() {
    int i = blockIdx.x * blockDim.x + threadIdx.x;
    if (i < BATCH * HID) g_h[0][i] = 0.0f;
    if (i == 0) g_ctr = 0u;
}

// ---------------- kernel A: xproj = gather(emb, x) @ W_ih^T + (b_ih + b_hh) ----------
// CTA tile 128(M) x 64(N), K-chunks of 32, tf32 mma m16n8k8.
// 8 warps as 4(M) x 2(N); warp tile 32x32 -> 2x4 mma tiles.
// Smem pitch 36: fragment LDS bank = (4g + 8ks + c) mod 32, conflict-free;
// float4 STS 16B-aligned (36*4 = 144 = 0 mod 16).
// Double-buffered smem + register staging: one __syncthreads per chunk.
__global__ void __launch_bounds__(256) embed_xproj_kernel(
    const int* __restrict__ x, const float* __restrict__ emb,
    const float* __restrict__ W_ih, const float* __restrict__ b_ih,
    const float* __restrict__ b_hh)
{
    extern __shared__ char smem_raw[];
    float* As = reinterpret_cast<float*>(smem_raw);                  // 2 x 128*36
    float* Bs = reinterpret_cast<float*>(smem_raw + 36864);          // 2 x 64*36
    int*   idx = reinterpret_cast<int*>(smem_raw + 36864 + 18432);   // 128

    const int tid = threadIdx.x;
    const int m0 = blockIdx.y * 128;
    const int n0 = blockIdx.x * 64;
    if (tid < 128) idx[tid] = x[m0 + tid];
    __syncthreads();

    const int warp = tid >> 5, lane = tid & 31;
    const int wm = warp >> 1, wn = warp & 1;
    const int g = lane >> 2, c = lane & 3;
    const int lrow = tid >> 3, lc4 = tid & 7;

    float4 aR[4], bR[2];
    auto load_regs = [&](int kc) {
#pragma unroll
        for (int i = 0; i < 4; i++) {
            int row = lrow + i * 32;
            aR[i] = *reinterpret_cast<const float4*>(
                &emb[(long)idx[row] * EMBD + kc + lc4 * 4]);
        }
#pragma unroll
        for (int i = 0; i < 2; i++) {
            int row = lrow + i * 32;
            bR[i] = *reinterpret_cast<const float4*>(
                &W_ih[(long)(n0 + row) * EMBD + kc + lc4 * 4]);
        }
    };
    auto sts_regs = [&](int buf) {
        float* Ab = &As[buf * 128 * 36];
        float* Bb = &Bs[buf * 64 * 36];
#pragma unroll
        for (int i = 0; i < 4; i++)
            *reinterpret_cast<float4*>(&Ab[(lrow + i * 32) * 36 + lc4 * 4]) = aR[i];
#pragma unroll
        for (int i = 0; i < 2; i++)
            *reinterpret_cast<float4*>(&Bb[(lrow + i * 32) * 36 + lc4 * 4]) = bR[i];
    };

    float acc[2][4][4];
#pragma unroll
    for (int mi = 0; mi < 2; mi++)
#pragma unroll
        for (int ni = 0; ni < 4; ni++)
#pragma unroll
            for (int j = 0; j < 4; j++) acc[mi][ni][j] = 0.0f;

    load_regs(0);
    sts_regs(0);
    __syncthreads();

    const int nchunk = EMBD / 32;
    for (int ch = 0; ch < nchunk; ch++) {
        const int cur = ch & 1;
        const float* Ab = &As[cur * 128 * 36];
        const float* Bb = &Bs[cur * 64 * 36];
        if (ch + 1 < nchunk) load_regs((ch + 1) * 32);

#pragma unroll
        for (int ks = 0; ks < 4; ks++) {
            uint32_t a[2][4], b[4][2];
#pragma unroll
            for (int mi = 0; mi < 2; mi++) {
                int r = wm * 32 + mi * 16 + g;
                int k0 = ks * 8 + c;
                a[mi][0] = f2tf32(Ab[r * 36 + k0]);
                a[mi][1] = f2tf32(Ab[(r + 8) * 36 + k0]);
                a[mi][2] = f2tf32(Ab[r * 36 + k0 + 4]);
                a[mi][3] = f2tf32(Ab[(r + 8) * 36 + k0 + 4]);
            }
#pragma unroll
            for (int ni = 0; ni < 4; ni++) {
                int n = wn * 32 + ni * 8 + g;
                int k0 = ks * 8 + c;
                b[ni][0] = f2tf32(Bb[n * 36 + k0]);
                b[ni][1] = f2tf32(Bb[n * 36 + k0 + 4]);
            }
#pragma unroll
            for (int mi = 0; mi < 2; mi++)
#pragma unroll
                for (int ni = 0; ni < 4; ni++)
                    mma_tf32(acc[mi][ni], a[mi], b[ni]);
        }

        if (ch + 1 < nchunk) sts_regs(1 - cur);
        __syncthreads();
    }

    // epilogue: add (b_ih + b_hh), store
#pragma unroll
    for (int mi = 0; mi < 2; mi++) {
#pragma unroll
        for (int ni = 0; ni < 4; ni++) {
            int r   = m0 + wm * 32 + mi * 16 + g;
            int col = n0 + wn * 32 + ni * 8 + c * 2;
            float bias0 = b_ih[col] + b_hh[col];
            float bias1 = b_ih[col + 1] + b_hh[col + 1];
            g_xproj[r * HID + col]           = acc[mi][ni][0] + bias0;
            g_xproj[r * HID + col + 1]       = acc[mi][ni][1] + bias1;
            g_xproj[(r + 8) * HID + col]     = acc[mi][ni][2] + bias0;
            g_xproj[(r + 8) * HID + col + 1] = acc[mi][ni][3] + bias1;
        }
    }
}

// ---------------- kernel B: persistent split-K RNN scan ----------------
// 128 CTAs = 16 N-slices x 8 K-splits, all co-resident (1 CTA/SM, smem 166KB).
// W_hh slice (128 x 256, tf32) resident in smem for all 256 steps.
// Per step:
//   GEMM: partial C[128, 128] over this CTA's 256-wide K-range (8 chunks of 32).
//   phase 1: all warps export full partial to g_part; all threads prefetch xproj
//            for this CTA's owned 16-row output stripe.  barrier A.
//   phase 2: all 256 threads fold 8 partials + xproj, tanh, write h stripe.
//            barrier B.
// L2 traffic/step: h 16MB + partials 16MB + xproj 1MB (vs 66MB at Ns=64,Ks=2).
__global__ void __launch_bounds__(256, 1) rnn_scan_kernel(
    const float* __restrict__ W_hh)
{
    extern __shared__ char smem_raw[];
    uint32_t* Ws = reinterpret_cast<uint32_t*>(smem_raw);                  // 128 x WS_PITCH
    float*    As = reinterpret_cast<float*>(smem_raw + 128 * WS_PITCH * 4); // 2 x 128*36

    const int tid  = threadIdx.x;
    const int warp = tid >> 5, lane = tid & 31;
    const int wm = warp >> 1, wn = warp & 1;
    const int g = lane >> 2, c = lane & 3;
    const int lrow = tid >> 3, lc4 = tid & 7;

    const int nsl   = blockIdx.x >> 3;          // 0..15
    const int kk    = blockIdx.x & 7;           // 0..7
    const int n0    = nsl * WN;
    const int kbase = kk * KC;
    const unsigned nCTA = gridDim.x;

    float* my_part = &g_part[(long)(nsl * KSPL + kk) * BATCH * WN];

    // ---- persistent W_hh slice -> smem (tf32), once ----
    {
        const int row  = tid >> 1;              // 0..127 (slice output col)
        const int half = tid & 1;
        const long base = (long)(n0 + row) * HID + kbase;
#pragma unroll 8
        for (int i = 0; i < 32; i++) {
            int j = half * 32 + i;              // float4 index 0..63
            const float4 v = *reinterpret_cast<const float4*>(&W_hh[base + j * 4]);
            uint4 u;
            u.x = f2tf32(v.x); u.y = f2tf32(v.y);
            u.z = f2tf32(v.z); u.w = f2tf32(v.w);
            *reinterpret_cast<uint4*>(&Ws[row * WS_PITCH + j * 4]) = u;
        }
    }
    __syncthreads();

    for (int t = 0; t < T_STEPS; t++) {
        const float* __restrict__ hin = g_h[t & 1];
        float* __restrict__ hout = g_h[(t + 1) & 1];

        float4 aR[4];
        auto load_regs = [&](int kc) {   // kc local to this CTA's K-range
#pragma unroll
            for (int i = 0; i < 4; i++) {
                int row = lrow + i * 32;
                aR[i] = *reinterpret_cast<const float4*>(
                    &hin[row * HID + kbase + kc + lc4 * 4]);
            }
        };
        auto sts_regs = [&](int buf) {
            float* Ab = &As[buf * 128 * 36];
#pragma unroll
            for (int i = 0; i < 4; i++)
                *reinterpret_cast<float4*>(&Ab[(lrow + i * 32) * 36 + lc4 * 4]) = aR[i];
        };

        float acc[2][8][4];
#pragma unroll
        for (int mi = 0; mi < 2; mi++)
#pragma unroll
            for (int ni = 0; ni < 8; ni++)
#pragma unroll
                for (int j = 0; j < 4; j++) acc[mi][ni][j] = 0.0f;

        load_regs(0);
        sts_regs(0);
        __syncthreads();

        const int nchunk = KC / 32;   // 8
        for (int ch = 0; ch < nchunk; ch++) {
            const int cur = ch & 1;
            const float* Ab = &As[cur * 128 * 36];
            if (ch + 1 < nchunk) load_regs((ch + 1) * 32);

#pragma unroll
            for (int ks = 0; ks < 4; ks++) {
                uint32_t a[2][4], b[8][2];
                const int kk0 = ch * 32 + ks * 8 + c;
#pragma unroll
                for (int mi = 0; mi < 2; mi++) {
                    int r = wm * 32 + mi * 16 + g;
                    int k0 = ks * 8 + c;
                    a[mi][0] = f2tf32(Ab[r * 36 + k0]);
                    a[mi][1] = f2tf32(Ab[(r + 8) * 36 + k0]);
                    a[mi][2] = f2tf32(Ab[r * 36 + k0 + 4]);
                    a[mi][3] = f2tf32(Ab[(r + 8) * 36 + k0 + 4]);
                }
#pragma unroll
                for (int ni = 0; ni < 8; ni++) {
                    int n = wn * 64 + ni * 8 + g;
                    b[ni][0] = Ws[n * WS_PITCH + kk0];
                    b[ni][1] = Ws[n * WS_PITCH + kk0 + 4];
                }
#pragma unroll
                for (int mi = 0; mi < 2; mi++)
#pragma unroll
                    for (int ni = 0; ni < 8; ni++)
                        mma_tf32(acc[mi][ni], a[mi], b[ni]);
            }

            if (ch + 1 < nchunk) sts_regs(1 - cur);
            __syncthreads();
        }

        // ---- phase 1: export full partial tile; prefetch xproj for owned stripe ----
#pragma unroll
        for (int mi = 0; mi < 2; mi++) {
#pragma unroll
            for (int ni = 0; ni < 8; ni++) {
                int r      = wm * 32 + mi * 16 + g;
                int colloc = wn * 64 + ni * 8 + c * 2;
                float2 v0 = make_float2(acc[mi][ni][0], acc[mi][ni][1]);
                float2 v1 = make_float2(acc[mi][ni][2], acc[mi][ni][3]);
                *reinterpret_cast<float2*>(&my_part[r * WN + colloc]) = v0;
                *reinterpret_cast<float2*>(&my_part[(r + 8) * WN + colloc]) = v1;
            }
        }

        // xproj prefetch: owned stripe = rows [16*kk, 16*kk+16) of this slice.
        float2 xp2[4];
#pragma unroll
        for (int w = 0; w < 4; w++) {
            int eid  = tid + w * 256;           // 0..1023
            int row  = eid >> 6;                // 0..15
            int col2 = eid & 63;
            int r    = kk * 16 + row;
            int colg = n0 + col2 * 2;
            xp2[w] = *reinterpret_cast<const float2*>(
                &g_xproj[(long)(t * BATCH + r) * HID + colg]);
        }

        // ---- grid barrier A: partials visible ----
        __threadfence();
        __syncthreads();
        if (tid == 0) grid_bar((unsigned)(2 * t + 1) * nCTA);
        __syncthreads();

        // ---- phase 2: fold 8 partials + xproj, tanh, write h stripe ----
#pragma unroll
        for (int w = 0; w < 4; w++) {
            int eid  = tid + w * 256;
            int row  = eid >> 6;
            int col2 = eid & 63;
            int r    = kk * 16 + row;
            int colg = n0 + col2 * 2;
            float sx = xp2[w].x, sy = xp2[w].y;
#pragma unroll
            for (int j = 0; j < KSPL; j++) {
                const float2 p = *reinterpret_cast<const float2*>(
                    &g_part[((long)(nsl * KSPL + j) * BATCH + r) * WN + col2 * 2]);
                sx += p.x; sy += p.y;
            }
            hout[r * HID + colg]     = tanhf(sx);
            hout[r * HID + colg + 1] = tanhf(sy);
        }

        // ---- grid barrier B: h(t+1) visible ----
        __threadfence();
        __syncthreads();
        if (tid == 0) grid_bar((unsigned)(2 * t + 2) * nCTA);
        __syncthreads();
    }
}

// ---------------- kernel C: MLP head ----------------
// 64 blocks x 2 batch rows. fc1 (2048->256, relu) then fc2 (256->3).
__global__ void __launch_bounds__(256) head_kernel(
    const float* __restrict__ fc1_w, const float* __restrict__ fc1_b,
    const float* __restrict__ fc2_w, const float* __restrict__ fc2_b,
    float* __restrict__ out)
{
    __shared__ float hs[HID];
    __shared__ float zs[2][256];
    const int tid = threadIdx.x;
    const int b0 = blockIdx.x * 2;

    for (int r = 0; r < 2; r++) {
        const float* hrow = &g_h[0][(b0 + r) * HID];   // T=256 even -> final h in buffer 0
        for (int i = tid; i < HID; i += 256) hs[i] = hrow[i];
        __syncthreads();

        float acc = fc1_b[tid];
        const float4* w = reinterpret_cast<const float4*>(&fc1_w[(long)tid * HID]);
#pragma unroll 8
        for (int k = 0; k < HID / 4; k++) {
            float4 wv = w[k];
            const float4 hv = *reinterpret_cast<const float4*>(&hs[k * 4]);
            acc += wv.x * hv.x + wv.y * hv.y + wv.z * hv.z + wv.w * hv.w;
        }
        zs[r][tid] = fmaxf(acc, 0.0f);
        __syncthreads();
    }

    // fc2: 6 warps -> (row, class)
    const int warp = tid >> 5, lane = tid & 31;
    if (warp < 6) {
        int r = warp / 3, cls = warp % 3;
        float p = 0.0f;
#pragma unroll
        for (int i = 0; i < 8; i++) {
            int j = lane + 32 * i;
            p += zs[r][j] * fc2_w[cls * 256 + j];
        }
#pragma unroll
        for (int off = 16; off; off >>= 1)
            p += __shfl_xor_sync(0xffffffffu, p, off);
        if (lane == 0) out[(b0 + r) * 3 + cls] = p + fc2_b[cls];
    }
}

// ---------------- launch ----------------
extern "C" void kernel_launch(void* const* d_in, const int* in_sizes, int n_in,
                              void* d_out, int out_size)
{
    (void)in_sizes; (void)n_in; (void)out_size;
    const int*   x     = (const int*)d_in[0];
    const float* emb   = (const float*)d_in[1];
    const float* W_ih  = (const float*)d_in[2];
    const float* W_hh  = (const float*)d_in[3];
    const float* b_ih  = (const float*)d_in[4];
    const float* b_hh  = (const float*)d_in[5];
    const float* fc1_w = (const float*)d_in[6];
    const float* fc1_b = (const float*)d_in[7];
    const float* fc2_w = (const float*)d_in[8];
    const float* fc2_b = (const float*)d_in[9];
    float* out = (float*)d_out;

    // Opt-in dynamic smem (idempotent; both kernels exceed the 48KB static limit).
    cudaFuncSetAttribute(embed_xproj_kernel,
                         cudaFuncAttributeMaxDynamicSharedMemorySize, EMB_SMEM);
    cudaFuncSetAttribute(rnn_scan_kernel,
                         cudaFuncAttributeMaxDynamicSharedMemorySize, SCAN_SMEM);

    init_kernel<<<(BATCH * HID + 255) / 256, 256>>>();

    dim3 gA(HID / 64, ROWS / 128);  // 32 x 256
    embed_xproj_kernel<<<gA, 256, EMB_SMEM>>>(x, emb, W_ih, b_ih, b_hh);

    rnn_scan_kernel<<<SCAN_CTAS, 256, SCAN_SMEM>>>(W_hh);

    head_kernel<<<64, 256>>>(fc1_w, fc1_b, fc2_w, fc2_b, out);
}

// round 8
// speedup vs baseline: 1.0688x; 1.0688x over previous
#include <cuda_runtime.h>
#include <cuda_bf16.h>
#include <cstdint>

// Problem: RNN_28621662060981
//   x[256,128] int32 -> emb[32000,2048] -> xproj GEMM -> 256-step tanh RNN -> MLP head
// Inputs (metadata order): x, emb, W_ih, W_hh, b_ih, b_hh, fc1_w, fc1_b, fc2_w, fc2_b
// Output: float32 [128,3]

#define T_STEPS 256
#define BATCH   128
#define EMBD    2048
#define HID     2048
#define ROWS    (T_STEPS * BATCH)   // 32768

// Scan decomposition: 16 N-slices (128 cols) x 8 K-splits (256 k) = 128 CTAs.
// (Traffic-optimal: h 16.8MB + partials 16.8MB per step; KSPL=4/16 both worse.)
#define NSL   16
#define KSPL  8
#define WN    128                   // output cols per slice
#define KC    256                   // k-range per CTA
#define SCAN_CTAS (NSL * KSPL)      // 128

// Smem (dynamic; static __shared__ limit is 48KB)
#define WS_PITCH 260                // 260 mod 32 = 4 -> b-fragment banks 4g+8ks+c, conflict-free
#define SCAN_SMEM (128 * WS_PITCH * 4 + 2 * 128 * 36 * 4)     // 133120 + 36864 = 169984
#define EMB_SMEM  (2 * 128 * 36 * 4 + 2 * 128 * 36 * 4 + 512) // 36864 + 36864 + 512 = 74240

// ---------------- scratch (device globals: allocation-free rule) ----------------
__device__ float    g_xproj[ROWS * HID];                  // 256 MB
__device__ float    g_h[2][BATCH * HID];                  // double-buffered hidden state
__device__ float    g_part[NSL * KSPL * BATCH * WN];      // 8.4 MB partial exchange
__device__ unsigned g_ctr;                                // grid barrier counter

// ---------------- helpers ----------------
__device__ __forceinline__ uint32_t f2tf32(float f) {
    uint32_t u;
    asm("cvt.rna.tf32.f32 %0, %1;" : "=r"(u) : "f"(f));
    return u;
}

__device__ __forceinline__ void mma_tf32(float* c, const uint32_t* a, const uint32_t* b) {
    asm volatile(
        "mma.sync.aligned.m16n8k8.row.col.f32.tf32.tf32.f32 "
        "{%0,%1,%2,%3}, {%4,%5,%6,%7}, {%8,%9}, {%0,%1,%2,%3};\n"
        : "+f"(c[0]), "+f"(c[1]), "+f"(c[2]), "+f"(c[3])
        : "r"(a[0]), "r"(a[1]), "r"(a[2]), "r"(a[3]), "r"(b[0]), "r"(b[1]));
}

// Grid barrier step (tid==0 only; bar.sync outside).
// red.release (no-return REDG) + acquire-poll with nanosleep backoff: avoids
// 128 CTAs hammering one LTS slice with back-to-back ld.acquire.
__device__ __forceinline__ void grid_bar(unsigned target) {
    asm volatile("red.release.gpu.global.add.u32 [%0], %1;"
                 :: "l"(&g_ctr), "r"(1u) : "memory");
    unsigned v;
    asm volatile("ld.acquire.gpu.global.u32 %0, [%1];" : "=r"(v) : "l"(&g_ctr));
    while (v < target) {
        __nanosleep(200);
        asm volatile("ld.acquire.gpu.global.u32 %0, [%1];" : "=r"(v) : "l"(&g_ctr));
    }
}

// ---------------- init: zero h0 + barrier counter (every launch, for graph replay) ----
__global__ void init_kernel() {
    int i = blockIdx.x * blockDim.x + threadIdx.x;
    if (i < BATCH * HID) g_h[0][i] = 0.0f;
    if (i == 0) g_ctr = 0u;
}

// ---------------- kernel A: xproj = gather(emb, x) @ W_ih^T + (b_ih + b_hh) ----------
// CTA tile 128(M) x 128(N), K-chunks of 32, tf32 mma m16n8k8.
// 8 warps as 4(M) x 2(N); warp tile 32x64 -> 2x8 mma tiles.
// Smem pitch 36: fragment LDS bank = (4g + 8ks + c) mod 32, conflict-free;
// float4 STS 16B-aligned (36*4 = 144 = 0 mod 16).
// Double-buffered smem + register staging: one __syncthreads per chunk.
// L2 traffic: A = 16 Nblk x 256MB = 4GB, B = 256 Mblk x 16MB = 4GB (was 12GB at Nt=64).
__global__ void __launch_bounds__(256) embed_xproj_kernel(
    const int* __restrict__ x, const float* __restrict__ emb,
    const float* __restrict__ W_ih, const float* __restrict__ b_ih,
    const float* __restrict__ b_hh)
{
    extern __shared__ char smem_raw[];
    float* As = reinterpret_cast<float*>(smem_raw);                  // 2 x 128*36
    float* Bs = reinterpret_cast<float*>(smem_raw + 36864);          // 2 x 128*36
    int*   idx = reinterpret_cast<int*>(smem_raw + 36864 + 36864);   // 128

    const int tid = threadIdx.x;
    const int m0 = blockIdx.y * 128;
    const int n0 = blockIdx.x * 128;
    if (tid < 128) idx[tid] = x[m0 + tid];
    __syncthreads();

    const int warp = tid >> 5, lane = tid & 31;
    const int wm = warp >> 1, wn = warp & 1;
    const int g = lane >> 2, c = lane & 3;
    const int lrow = tid >> 3, lc4 = tid & 7;

    float4 aR[4], bR[4];
    auto load_regs = [&](int kc) {
#pragma unroll
        for (int i = 0; i < 4; i++) {
            int row = lrow + i * 32;
            aR[i] = *reinterpret_cast<const float4*>(
                &emb[(long)idx[row] * EMBD + kc + lc4 * 4]);
        }
#pragma unroll
        for (int i = 0; i < 4; i++) {
            int row = lrow + i * 32;
            bR[i] = *reinterpret_cast<const float4*>(
                &W_ih[(long)(n0 + row) * EMBD + kc + lc4 * 4]);
        }
    };
    auto sts_regs = [&](int buf) {
        float* Ab = &As[buf * 128 * 36];
        float* Bb = &Bs[buf * 128 * 36];
#pragma unroll
        for (int i = 0; i < 4; i++)
            *reinterpret_cast<float4*>(&Ab[(lrow + i * 32) * 36 + lc4 * 4]) = aR[i];
#pragma unroll
        for (int i = 0; i < 4; i++)
            *reinterpret_cast<float4*>(&Bb[(lrow + i * 32) * 36 + lc4 * 4]) = bR[i];
    };

    float acc[2][8][4];
#pragma unroll
    for (int mi = 0; mi < 2; mi++)
#pragma unroll
        for (int ni = 0; ni < 8; ni++)
#pragma unroll
            for (int j = 0; j < 4; j++) acc[mi][ni][j] = 0.0f;

    load_regs(0);
    sts_regs(0);
    __syncthreads();

    const int nchunk = EMBD / 32;
    for (int ch = 0; ch < nchunk; ch++) {
        const int cur = ch & 1;
        const float* Ab = &As[cur * 128 * 36];
        const float* Bb = &Bs[cur * 128 * 36];
        if (ch + 1 < nchunk) load_regs((ch + 1) * 32);

#pragma unroll
        for (int ks = 0; ks < 4; ks++) {
            uint32_t a[2][4], b[8][2];
#pragma unroll
            for (int mi = 0; mi < 2; mi++) {
                int r = wm * 32 + mi * 16 + g;
                int k0 = ks * 8 + c;
                a[mi][0] = f2tf32(Ab[r * 36 + k0]);
                a[mi][1] = f2tf32(Ab[(r + 8) * 36 + k0]);
                a[mi][2] = f2tf32(Ab[r * 36 + k0 + 4]);
                a[mi][3] = f2tf32(Ab[(r + 8) * 36 + k0 + 4]);
            }
#pragma unroll
            for (int ni = 0; ni < 8; ni++) {
                int n = wn * 64 + ni * 8 + g;
                int k0 = ks * 8 + c;
                b[ni][0] = f2tf32(Bb[n * 36 + k0]);
                b[ni][1] = f2tf32(Bb[n * 36 + k0 + 4]);
            }
#pragma unroll
            for (int mi = 0; mi < 2; mi++)
#pragma unroll
                for (int ni = 0; ni < 8; ni++)
                    mma_tf32(acc[mi][ni], a[mi], b[ni]);
        }

        if (ch + 1 < nchunk) sts_regs(1 - cur);
        __syncthreads();
    }

    // epilogue: add (b_ih + b_hh), store
#pragma unroll
    for (int mi = 0; mi < 2; mi++) {
#pragma unroll
        for (int ni = 0; ni < 8; ni++) {
            int r   = m0 + wm * 32 + mi * 16 + g;
            int col = n0 + wn * 64 + ni * 8 + c * 2;
            float bias0 = b_ih[col] + b_hh[col];
            float bias1 = b_ih[col + 1] + b_hh[col + 1];
            g_xproj[r * HID + col]           = acc[mi][ni][0] + bias0;
            g_xproj[r * HID + col + 1]       = acc[mi][ni][1] + bias1;
            g_xproj[(r + 8) * HID + col]     = acc[mi][ni][2] + bias0;
            g_xproj[(r + 8) * HID + col + 1] = acc[mi][ni][3] + bias1;
        }
    }
}

// ---------------- kernel B: persistent split-K RNN scan ----------------
// 128 CTAs = 16 N-slices x 8 K-splits, all co-resident (1 CTA/SM, smem 166KB).
// W_hh slice (128 x 256, tf32) resident in smem for all 256 steps.
// GEMM structure identical to the measured round-3 kernel; only the grid
// barrier implementation changed (red.release + nanosleep backoff).
__global__ void __launch_bounds__(256, 1) rnn_scan_kernel(
    const float* __restrict__ W_hh)
{
    extern __shared__ char smem_raw[];
    uint32_t* Ws = reinterpret_cast<uint32_t*>(smem_raw);                  // 128 x WS_PITCH
    float*    As = reinterpret_cast<float*>(smem_raw + 128 * WS_PITCH * 4); // 2 x 128*36

    const int tid  = threadIdx.x;
    const int warp = tid >> 5, lane = tid & 31;
    const int wm = warp >> 1, wn = warp & 1;
    const int g = lane >> 2, c = lane & 3;
    const int lrow = tid >> 3, lc4 = tid & 7;

    const int nsl   = blockIdx.x >> 3;          // 0..15
    const int kk    = blockIdx.x & 7;           // 0..7
    const int n0    = nsl * WN;
    const int kbase = kk * KC;
    const unsigned nCTA = gridDim.x;

    float* my_part = &g_part[(long)(nsl * KSPL + kk) * BATCH * WN];

    // ---- persistent W_hh slice -> smem (tf32), once ----
    {
        const int row  = tid >> 1;              // 0..127 (slice output col)
        const int half = tid & 1;
        const long base = (long)(n0 + row) * HID + kbase;
#pragma unroll 8
        for (int i = 0; i < 32; i++) {
            int j = half * 32 + i;              // float4 index 0..63
            const float4 v = *reinterpret_cast<const float4*>(&W_hh[base + j * 4]);
            uint4 u;
            u.x = f2tf32(v.x); u.y = f2tf32(v.y);
            u.z = f2tf32(v.z); u.w = f2tf32(v.w);
            *reinterpret_cast<uint4*>(&Ws[row * WS_PITCH + j * 4]) = u;
        }
    }
    __syncthreads();

    for (int t = 0; t < T_STEPS; t++) {
        const float* __restrict__ hin = g_h[t & 1];
        float* __restrict__ hout = g_h[(t + 1) & 1];

        float4 aR[4];
        auto load_regs = [&](int kc) {   // kc local to this CTA's K-range
#pragma unroll
            for (int i = 0; i < 4; i++) {
                int row = lrow + i * 32;
                aR[i] = *reinterpret_cast<const float4*>(
                    &hin[row * HID + kbase + kc + lc4 * 4]);
            }
        };
        auto sts_regs = [&](int buf) {
            float* Ab = &As[buf * 128 * 36];
#pragma unroll
            for (int i = 0; i < 4; i++)
                *reinterpret_cast<float4*>(&Ab[(lrow + i * 32) * 36 + lc4 * 4]) = aR[i];
        };

        float acc[2][8][4];
#pragma unroll
        for (int mi = 0; mi < 2; mi++)
#pragma unroll
            for (int ni = 0; ni < 8; ni++)
#pragma unroll
                for (int j = 0; j < 4; j++) acc[mi][ni][j] = 0.0f;

        load_regs(0);
        sts_regs(0);
        __syncthreads();

        const int nchunk = KC / 32;   // 8
        for (int ch = 0; ch < nchunk; ch++) {
            const int cur = ch & 1;
            const float* Ab = &As[cur * 128 * 36];
            if (ch + 1 < nchunk) load_regs((ch + 1) * 32);

#pragma unroll
            for (int ks = 0; ks < 4; ks++) {
                uint32_t a[2][4], b[8][2];
                const int kk0 = ch * 32 + ks * 8 + c;
#pragma unroll
                for (int mi = 0; mi < 2; mi++) {
                    int r = wm * 32 + mi * 16 + g;
                    int k0 = ks * 8 + c;
                    a[mi][0] = f2tf32(Ab[r * 36 + k0]);
                    a[mi][1] = f2tf32(Ab[(r + 8) * 36 + k0]);
                    a[mi][2] = f2tf32(Ab[r * 36 + k0 + 4]);
                    a[mi][3] = f2tf32(Ab[(r + 8) * 36 + k0 + 4]);
                }
#pragma unroll
                for (int ni = 0; ni < 8; ni++) {
                    int n = wn * 64 + ni * 8 + g;
                    b[ni][0] = Ws[n * WS_PITCH + kk0];
                    b[ni][1] = Ws[n * WS_PITCH + kk0 + 4];
                }
#pragma unroll
                for (int mi = 0; mi < 2; mi++)
#pragma unroll
                    for (int ni = 0; ni < 8; ni++)
                        mma_tf32(acc[mi][ni], a[mi], b[ni]);
            }

            if (ch + 1 < nchunk) sts_regs(1 - cur);
            __syncthreads();
        }

        // ---- phase 1: export full partial tile; prefetch xproj for owned stripe ----
#pragma unroll
        for (int mi = 0; mi < 2; mi++) {
#pragma unroll
            for (int ni = 0; ni < 8; ni++) {
                int r      = wm * 32 + mi * 16 + g;
                int colloc = wn * 64 + ni * 8 + c * 2;
                float2 v0 = make_float2(acc[mi][ni][0], acc[mi][ni][1]);
                float2 v1 = make_float2(acc[mi][ni][2], acc[mi][ni][3]);
                *reinterpret_cast<float2*>(&my_part[r * WN + colloc]) = v0;
                *reinterpret_cast<float2*>(&my_part[(r + 8) * WN + colloc]) = v1;
            }
        }

        // xproj prefetch: owned stripe = rows [16*kk, 16*kk+16) of this slice.
        float2 xp2[4];
#pragma unroll
        for (int w = 0; w < 4; w++) {
            int eid  = tid + w * 256;           // 0..1023
            int row  = eid >> 6;                // 0..15
            int col2 = eid & 63;
            int r    = kk * 16 + row;
            int colg = n0 + col2 * 2;
            xp2[w] = *reinterpret_cast<const float2*>(
                &g_xproj[(long)(t * BATCH + r) * HID + colg]);
        }

        // ---- grid barrier A: partials visible ----
        __threadfence();
        __syncthreads();
        if (tid == 0) grid_bar((unsigned)(2 * t + 1) * nCTA);
        __syncthreads();

        // ---- phase 2: fold 8 partials + xproj, tanh, write h stripe ----
#pragma unroll
        for (int w = 0; w < 4; w++) {
            int eid  = tid + w * 256;
            int row  = eid >> 6;
            int col2 = eid & 63;
            int r    = kk * 16 + row;
            int colg = n0 + col2 * 2;
            float sx = xp2[w].x, sy = xp2[w].y;
#pragma unroll
            for (int j = 0; j < KSPL; j++) {
                const float2 p = *reinterpret_cast<const float2*>(
                    &g_part[((long)(nsl * KSPL + j) * BATCH + r) * WN + col2 * 2]);
                sx += p.x; sy += p.y;
            }
            hout[r * HID + colg]     = tanhf(sx);
            hout[r * HID + colg + 1] = tanhf(sy);
        }

        // ---- grid barrier B: h(t+1) visible ----
        __threadfence();
        __syncthreads();
        if (tid == 0) grid_bar((unsigned)(2 * t + 2) * nCTA);
        __syncthreads();
    }
}

// ---------------- kernel C: MLP head ----------------
// 128 blocks (one batch row each); 256 threads = one fc1 neuron each.
// 4 independent accumulators break the serial FMA chain (4x ILP).
__global__ void __launch_bounds__(256) head_kernel(
    const float* __restrict__ fc1_w, const float* __restrict__ fc1_b,
    const float* __restrict__ fc2_w, const float* __restrict__ fc2_b,
    float* __restrict__ out)
{
    __shared__ float hs[HID];
    __shared__ float zs[256];
    const int tid = threadIdx.x;
    const int brow = blockIdx.x;

    const float* hrow = &g_h[0][brow * HID];   // T=256 even -> final h in buffer 0
    for (int i = tid; i < HID; i += 256) hs[i] = hrow[i];
    __syncthreads();

    float a0 = 0.f, a1 = 0.f, a2 = 0.f, a3 = 0.f;
    const float4* w = reinterpret_cast<const float4*>(&fc1_w[(long)tid * HID]);
#pragma unroll 8
    for (int k = 0; k < HID / 4; k++) {
        float4 wv = w[k];
        const float4 hv = *reinterpret_cast<const float4*>(&hs[k * 4]);
        a0 += wv.x * hv.x; a1 += wv.y * hv.y;
        a2 += wv.z * hv.z; a3 += wv.w * hv.w;
    }
    zs[tid] = fmaxf((a0 + a1) + (a2 + a3) + fc1_b[tid], 0.0f);
    __syncthreads();

    // fc2: warps 0-2 -> one class each; 256-length dot via 8 elems/lane + shuffle.
    const int warp = tid >> 5, lane = tid & 31;
    if (warp < 3) {
        int cls = warp;
        float p = 0.0f;
#pragma unroll
        for (int i = 0; i < 8; i++) {
            int j = lane + 32 * i;
            p += zs[j] * fc2_w[cls * 256 + j];
        }
#pragma unroll
        for (int off = 16; off; off >>= 1)
            p += __shfl_xor_sync(0xffffffffu, p, off);
        if (lane == 0) out[brow * 3 + cls] = p + fc2_b[cls];
    }
}

// ---------------- launch ----------------
extern "C" void kernel_launch(void* const* d_in, const int* in_sizes, int n_in,
                              void* d_out, int out_size)
{
    (void)in_sizes; (void)n_in; (void)out_size;
    const int*   x     = (const int*)d_in[0];
    const float* emb   = (const float*)d_in[1];
    const float* W_ih  = (const float*)d_in[2];
    const float* W_hh  = (const float*)d_in[3];
    const float* b_ih  = (const float*)d_in[4];
    const float* b_hh  = (const float*)d_in[5];
    const float* fc1_w = (const float*)d_in[6];
    const float* fc1_b = (const float*)d_in[7];
    const float* fc2_w = (const float*)d_in[8];
    const float* fc2_b = (const float*)d_in[9];
    float* out = (float*)d_out;

    // Opt-in dynamic smem (idempotent; both kernels exceed the 48KB static limit).
    cudaFuncSetAttribute(embed_xproj_kernel,
                         cudaFuncAttributeMaxDynamicSharedMemorySize, EMB_SMEM);
    cudaFuncSetAttribute(rnn_scan_kernel,
                         cudaFuncAttributeMaxDynamicSharedMemorySize, SCAN_SMEM);

    init_kernel<<<(BATCH * HID + 255) / 256, 256>>>();

    dim3 gA(HID / 128, ROWS / 128);  // 16 x 256
    embed_xproj_kernel<<<gA, 256, EMB_SMEM>>>(x, emb, W_ih, b_ih, b_hh);

    rnn_scan_kernel<<<SCAN_CTAS, 256, SCAN_SMEM>>>(W_hh);

    head_kernel<<<BATCH, 256>>>(fc1_w, fc1_b, fc2_w, fc2_b, out);
}